// round 1
// baseline (speedup 1.0000x reference)
#include <cuda_runtime.h>
#include <cstdint>

#define TILE_M   256
#define THREADS  256
#define CIN      32
#define COUT     32
#define KVOL     27
#define XS_STRIDE 260   // 256 rows + 4 floats pad: keeps 16B alignment, rotates banks by 4/c-row

// Flag: 1 if kmap_valid is 1 byte per element (numpy bool), 0 if int32.
__device__ int g_valid_is_u8;

__global__ void detect_valid_dtype(const unsigned char* __restrict__ v, int nbytes) {
    int nz = 0;
    for (int i = threadIdx.x; i < nbytes; i += 32) {
        if ((i & 3) && v[i]) nz = 1;
    }
    nz = __any_sync(0xffffffffu, nz);
    if (threadIdx.x == 0) g_valid_is_u8 = nz;   // any nonzero off-word byte => u8 layout
}

__global__ void __launch_bounds__(THREADS, 2)
sparse_conv_kernel(const float* __restrict__ feat,
                   const float* __restrict__ weight,
                   const float* __restrict__ bias,
                   const int* __restrict__ kidx,
                   const unsigned char* __restrict__ kvalid,
                   float* __restrict__ out,
                   int N)
{
    __shared__ float xs[CIN * XS_STRIDE];   // transposed gathered tile: xs[c][row]
    __shared__ float ws[CIN * COUT];        // current tap weights [c][j]

    const int tid   = threadIdx.x;
    const int tm    = tid >> 3;             // 0..31 -> rows tm*8 .. tm*8+7
    const int tn    = tid & 7;              // 0..7  -> cols tn*4 .. tn*4+3
    const int base  = blockIdx.x * TILE_M;
    const int row_g = base + tid;           // gather row owned by this thread
    const bool u8   = (g_valid_is_u8 != 0);
    const int* kvalid32 = (const int*)kvalid;

    float acc[8][4];
    #pragma unroll
    for (int i = 0; i < 8; i++)
        #pragma unroll
        for (int j = 0; j < 4; j++) acc[i][j] = 0.0f;

    float4 px[8];   // prefetched gathered row (32 floats)
    float4 pw;      // prefetched weight chunk (4 floats)

    // ---- prefetch tap 0 ----
    {
        bool v = false;
        int idx = 0;
        if (row_g < N) {
            idx = kidx[row_g];
            v = u8 ? (kvalid[row_g] != 0) : (kvalid32[row_g] != 0);
        }
        if (v) {
            const float4* src = (const float4*)(feat + (size_t)idx * CIN);
            #pragma unroll
            for (int q = 0; q < 8; q++) px[q] = src[q];
        } else {
            #pragma unroll
            for (int q = 0; q < 8; q++) px[q] = make_float4(0.f, 0.f, 0.f, 0.f);
        }
        pw = ((const float4*)weight)[tid];
    }

    for (int k = 0; k < KVOL; k++) {
        __syncthreads();   // xs/ws free to overwrite

        // stage prefetched data into smem (x transposed: conflict-free STS, all 32 banks)
        #pragma unroll
        for (int q = 0; q < 8; q++) {
            xs[(q * 4 + 0) * XS_STRIDE + tid] = px[q].x;
            xs[(q * 4 + 1) * XS_STRIDE + tid] = px[q].y;
            xs[(q * 4 + 2) * XS_STRIDE + tid] = px[q].z;
            xs[(q * 4 + 3) * XS_STRIDE + tid] = px[q].w;
        }
        ((float4*)ws)[tid] = pw;

        __syncthreads();

        // ---- issue prefetch for tap k+1 (overlaps with compute below) ----
        if (k + 1 < KVOL) {
            const int koff = (k + 1) * N;
            bool v = false;
            int idx = 0;
            if (row_g < N) {
                idx = kidx[koff + row_g];
                v = u8 ? (kvalid[koff + row_g] != 0) : (kvalid32[koff + row_g] != 0);
            }
            if (v) {
                const float4* src = (const float4*)(feat + (size_t)idx * CIN);
                #pragma unroll
                for (int q = 0; q < 8; q++) px[q] = src[q];
            } else {
                #pragma unroll
                for (int q = 0; q < 8; q++) px[q] = make_float4(0.f, 0.f, 0.f, 0.f);
            }
            pw = ((const float4*)(weight + (size_t)(k + 1) * CIN * COUT))[tid];
        }

        // ---- compute: 8x4 register tile, 32 FMA per 48B of LDS ----
        #pragma unroll
        for (int c = 0; c < CIN; c++) {
            const float* xr = xs + c * XS_STRIDE + tm * 8;
            float4 xa = *(const float4*)(xr);
            float4 xb = *(const float4*)(xr + 4);
            float4 wv = *(const float4*)(ws + c * COUT + tn * 4);
            float xv[8] = {xa.x, xa.y, xa.z, xa.w, xb.x, xb.y, xb.z, xb.w};
            float wf[4] = {wv.x, wv.y, wv.z, wv.w};
            #pragma unroll
            for (int i = 0; i < 8; i++)
                #pragma unroll
                for (int j = 0; j < 4; j++)
                    acc[i][j] += xv[i] * wf[j];
        }
    }

    // ---- bias + store ----
    float4 bv = *(const float4*)(bias + tn * 4);
    #pragma unroll
    for (int i = 0; i < 8; i++) {
        int r = base + tm * 8 + i;
        if (r < N) {
            float4 o;
            o.x = acc[i][0] + bv.x;
            o.y = acc[i][1] + bv.y;
            o.z = acc[i][2] + bv.z;
            o.w = acc[i][3] + bv.w;
            *(float4*)(out + (size_t)r * COUT + tn * 4) = o;
        }
    }
}

extern "C" void kernel_launch(void* const* d_in, const int* in_sizes, int n_in,
                              void* d_out, int out_size) {
    const float*         feat   = (const float*)d_in[0];          // [N, 32]
    const float*         weight = (const float*)d_in[1];          // [27, 32, 32]
    const float*         bias   = (const float*)d_in[2];          // [32]
    const int*           kidx   = (const int*)d_in[3];            // [27, N]
    const unsigned char* kvalid = (const unsigned char*)d_in[4];  // [27, N] bool (u8 or i32)
    float* out = (float*)d_out;

    const int N = in_sizes[0] / CIN;

    detect_valid_dtype<<<1, 32>>>(kvalid, 16384);

    const int grid = (N + TILE_M - 1) / TILE_M;
    sparse_conv_kernel<<<grid, THREADS>>>(feat, weight, bias, kidx, kvalid, out, N);
}

// round 3
// speedup vs baseline: 1.4708x; 1.4708x over previous
#include <cuda_runtime.h>
#include <cstdint>

#define CIN     32
#define COUT    32
#define KVOL    27
#define TILE    128
#define SUPER   2
#define ROWS_ST (SUPER * TILE)        // 256 rows per supertile
#define NSTAGE  3
#define THREADS 256
#define W_TAP   4096                  // bytes of packed frags per tap
#define WBYTES  (KVOL * W_TAP)        // 110592
#define ASTAGE  (ROWS_ST * 128)       // 32768 bytes per stage
#define SMEM_TOTAL (WBYTES + NSTAGE * ASTAGE)   // 208896

__device__ int g_valid_is_u8;

__global__ void detect_valid_dtype(const unsigned char* __restrict__ v, int nbytes) {
    int nz = 0;
    for (int i = threadIdx.x; i < nbytes; i += 32)
        if ((i & 3) && v[i]) nz = 1;
    nz = __any_sync(0xffffffffu, nz);
    if (threadIdx.x == 0) g_valid_is_u8 = nz;
}

// ---------------- helpers ----------------
__device__ __forceinline__ uint32_t smem_u32(const void* p) {
    uint32_t a;
    asm("{ .reg .u64 t; cvta.to.shared.u64 t, %1; cvt.u32.u64 %0, t; }" : "=r"(a) : "l"(p));
    return a;
}
__device__ __forceinline__ void cp16(uint32_t dst, const void* src, uint32_t nbytes) {
    asm volatile("cp.async.cg.shared.global [%0], [%1], 16, %2;"
                 :: "r"(dst), "l"(src), "r"(nbytes) : "memory");
}
#define CP_COMMIT() asm volatile("cp.async.commit_group;" ::: "memory")
#define CP_WAIT1()  asm volatile("cp.async.wait_group 1;" ::: "memory")

__device__ __forceinline__ uint32_t f2tf32(float f) {
    uint32_t t;
    asm("cvt.rna.tf32.f32 %0, %1;" : "=r"(t) : "f"(f));
    return t;
}
__device__ __forceinline__ void mma_tf32(float& d0, float& d1, float& d2, float& d3,
                                         uint32_t a0, uint32_t a1, uint32_t a2, uint32_t a3,
                                         uint32_t b0, uint32_t b1) {
    asm volatile(
        "mma.sync.aligned.m16n8k8.row.col.f32.tf32.tf32.f32 "
        "{%0,%1,%2,%3}, {%4,%5,%6,%7}, {%8,%9}, {%0,%1,%2,%3};"
        : "+f"(d0), "+f"(d1), "+f"(d2), "+f"(d3)
        : "r"(a0), "r"(a1), "r"(a2), "r"(a3), "r"(b0), "r"(b1));
}

struct Pref { int idx[8]; unsigned val; };

// ---------------- main kernel ----------------
__global__ void __launch_bounds__(THREADS, 1)
spconv_mma(const float* __restrict__ feat,
           const float* __restrict__ weight,
           const float* __restrict__ bias,
           const int* __restrict__ kidx,
           const unsigned char* __restrict__ kvalid,
           float* __restrict__ out,
           int N)
{
    extern __shared__ __align__(16) char smem[];
    const uint32_t sb  = smem_u32(smem);
    const uint32_t sbA = sb + WBYTES;

    const int tid  = threadIdx.x;
    const int w    = tid >> 5;
    const int lane = tid & 31;
    const int gid  = lane >> 2;    // 0..7
    const int tig  = lane & 3;     // 0..3
    const bool u8  = (g_valid_is_u8 != 0);
    const int* kvalid32 = (const int*)kvalid;

    const int nsup = (N + ROWS_ST - 1) / ROWS_ST;        // supertiles
    const int G    = gridDim.x;

    // ---- pack weights into smem: per tap 8 dfrags of 512B, lane-ordered ----
    // dfrag p holds frags f=2p,2p+1 (f = ks*4+nt); per lane: [b0(f0),b1(f0),b0(f1),b1(f1)]
    // b0 = W[tap][ks*8+tig][nt*8+gid], b1 = W[tap][ks*8+tig+4][nt*8+gid]
    for (int i = tid; i < KVOL * 1024; i += THREADS) {
        int tap = i >> 10, d = i & 1023;
        int p = d >> 7, ln = (d >> 2) & 31, q = d & 3;
        int f = 2 * p + (q >> 1);
        int ks = f >> 2, nt = f & 3;
        int tg = ln & 3, gd = ln >> 2;
        int c = ks * 8 + tg + ((q & 1) ? 4 : 0);
        int j = nt * 8 + gd;
        ((uint32_t*)smem)[(size_t)tap * 1024 + d] = f2tf32(weight[(size_t)tap * 1024 + c * 32 + j]);
    }
    __syncthreads();

    // ---- bias fragments ----
    float2 bb[4];
    #pragma unroll
    for (int nt = 0; nt < 4; nt++) {
        bb[nt].x = bias[nt * 8 + tig * 2 + 0];
        bb[nt].y = bias[nt * 8 + tig * 2 + 1];
    }

    // my supertile count
    int myS = 0;
    for (int s = blockIdx.x; s < nsup; s += G) myS++;
    const int total = myS * KVOL;
    if (total == 0) return;

    // gather addressing: thread owns rows r0+32q (q=0..7), chunk = tid&7
    const int r0 = tid >> 3;
    const int ch = tid & 7;
    const uint32_t dst0 = (uint32_t)r0 * 128 + (uint32_t)((ch ^ (r0 & 7)) << 4);
    const char* fbase = (const char*)feat;

    // idx/valid prefetch for job (S, tap)
    auto load_idx = [&](int S, int tap, Pref& P) {
        int base = S * ROWS_ST + r0;
        unsigned vm = 0;
        #pragma unroll
        for (int q = 0; q < 8; q++) {
            int g = base + 32 * q;
            int id = 0;
            bool va = false;
            if (g < N) {
                size_t o = (size_t)tap * N + g;
                id = kidx[o];
                va = u8 ? (kvalid[o] != 0) : (kvalid32[o] != 0);
            }
            P.idx[q] = id;
            vm |= va ? (1u << q) : 0u;
        }
        P.val = vm;
    };
    auto issue = [&](const Pref& P, int stage) {
        uint32_t ab = sbA + (uint32_t)stage * ASTAGE + dst0;
        #pragma unroll
        for (int q = 0; q < 8; q++) {
            const char* src = fbase + ((size_t)(uint32_t)P.idx[q] << 7) + (ch << 4);
            cp16(ab + q * 4096u, src, ((P.val >> q) & 1u) ? 16u : 0u);
        }
    };

    // ---- prologue: jobs 0,1 issued; job 2 idx prefetched ----
    Pref Pa;
    load_idx(blockIdx.x, 0, Pa);
    issue(Pa, 0); CP_COMMIT();
    if (total > 1) { load_idx(blockIdx.x, 1, Pa); issue(Pa, 1); }
    CP_COMMIT();
    if (total > 2) load_idx(blockIdx.x, 2, Pa);

    int ptap = 3, pS = blockIdx.x;                 // prefetch stream (job jl+3)
    if (ptap >= KVOL) { ptap -= KVOL; pS += G; }
    int ctap = 0, cS = blockIdx.x;                 // compute stream (job jl)

    float acc[2][4][4];
    #pragma unroll
    for (int T = 0; T < 2; T++)
        #pragma unroll
        for (int nt = 0; nt < 4; nt++)
            #pragma unroll
            for (int r = 0; r < 4; r++) acc[T][nt][r] = 0.0f;

    for (int jl = 0; jl < total; jl++) {
        CP_WAIT1();
        __syncthreads();

        // issue gather for job jl+2 (idx prefetched last iteration)
        if (jl + 2 < total) issue(Pa, (jl + 2) % NSTAGE);
        CP_COMMIT();

        // prefetch idx for job jl+3
        if (jl + 3 < total) {
            load_idx(pS, ptap, Pa);
            if (++ptap == KVOL) { ptap = 0; pS += G; }
        }

        // ---- compute tap ctap of supertile cS from stage jl%NSTAGE ----
        const char* Ab = smem + WBYTES + (size_t)(jl % NSTAGE) * ASTAGE;

        // B fragments for this tap: 8x LDS.128, conflict-free
        float4 bf[8];
        const float4* wp = (const float4*)(smem + (size_t)ctap * W_TAP);
        #pragma unroll
        for (int p = 0; p < 8; p++) bf[p] = wp[p * 32 + lane];

        #pragma unroll
        for (int T = 0; T < 2; T++) {
            const int rA = T * 128 + w * 16 + gid;       // rA&7 == gid
            const int rB = rA + 8;                       // rB&7 == gid
            const char* pA = Ab + (size_t)rA * 128;
            const char* pB = Ab + (size_t)rB * 128;
            #pragma unroll
            for (int ks = 0; ks < 4; ks++) {
                const uint32_t c0 = (uint32_t)(((2 * ks) ^ gid) << 4) + tig * 4;
                const uint32_t c1 = (uint32_t)(((2 * ks + 1) ^ gid) << 4) + tig * 4;
                uint32_t a0 = f2tf32(*(const float*)(pA + c0));
                uint32_t a1 = f2tf32(*(const float*)(pB + c0));
                uint32_t a2 = f2tf32(*(const float*)(pA + c1));
                uint32_t a3 = f2tf32(*(const float*)(pB + c1));
                #pragma unroll
                for (int nt = 0; nt < 4; nt++) {
                    float4 v = bf[ks * 2 + (nt >> 1)];
                    uint32_t b0 = (nt & 1) ? __float_as_uint(v.z) : __float_as_uint(v.x);
                    uint32_t b1 = (nt & 1) ? __float_as_uint(v.w) : __float_as_uint(v.y);
                    mma_tf32(acc[T][nt][0], acc[T][nt][1], acc[T][nt][2], acc[T][nt][3],
                             a0, a1, a2, a3, b0, b1);
                }
            }
        }

        // ---- end of supertile: epilogue ----
        if (++ctap == KVOL) {
            #pragma unroll
            for (int T = 0; T < 2; T++) {
                int gr = cS * ROWS_ST + T * 128 + w * 16 + gid;
                #pragma unroll
                for (int nt = 0; nt < 4; nt++) {
                    int col = nt * 8 + tig * 2;
                    if (gr < N) {
                        float2 o = { acc[T][nt][0] + bb[nt].x, acc[T][nt][1] + bb[nt].y };
                        *(float2*)(out + (size_t)gr * COUT + col) = o;
                    }
                    if (gr + 8 < N) {
                        float2 o = { acc[T][nt][2] + bb[nt].x, acc[T][nt][3] + bb[nt].y };
                        *(float2*)(out + (size_t)(gr + 8) * COUT + col) = o;
                    }
                    acc[T][nt][0] = acc[T][nt][1] = acc[T][nt][2] = acc[T][nt][3] = 0.0f;
                }
            }
            ctap = 0;
            cS += G;
        }
    }
}

extern "C" void kernel_launch(void* const* d_in, const int* in_sizes, int n_in,
                              void* d_out, int out_size) {
    const float*         feat   = (const float*)d_in[0];          // [N, 32]
    const float*         weight = (const float*)d_in[1];          // [27, 32, 32]
    const float*         bias   = (const float*)d_in[2];          // [32]
    const int*           kidx   = (const int*)d_in[3];            // [27, N]
    const unsigned char* kvalid = (const unsigned char*)d_in[4];  // [27, N] bool
    float* out = (float*)d_out;

    const int N = in_sizes[0] / CIN;

    int sms = 148;
    cudaDeviceGetAttribute(&sms, cudaDevAttrMultiProcessorCount, 0);

    cudaFuncSetAttribute(spconv_mma, cudaFuncAttributeMaxDynamicSharedMemorySize, SMEM_TOTAL);

    detect_valid_dtype<<<1, 32>>>(kvalid, 16384);
    spconv_mma<<<sms, THREADS, SMEM_TOTAL>>>(feat, weight, bias, kidx, kvalid, out, N);
}

// round 4
// speedup vs baseline: 2.4767x; 1.6839x over previous
#include <cuda_runtime.h>
#include <cstdint>

#define CIN     32
#define COUT    32
#define KVOL    27
#define WARPS   16
#define THREADS 512
#define NSTAGE  3
#define ROWS_W  16                      // rows per warp-tile
#define SLICE   2048                    // 16 rows * 128 B per warp-stage
#define W_TAP   4096
#define WBYTES  (KVOL * W_TAP)          // 110592
#define SMEM_TOTAL (WBYTES + WARPS * NSTAGE * SLICE)   // 208896

__device__ int g_valid_is_u8;

__global__ void detect_valid_dtype(const unsigned char* __restrict__ v, int nbytes) {
    int nz = 0;
    for (int i = threadIdx.x; i < nbytes; i += 32)
        if ((i & 3) && v[i]) nz = 1;
    nz = __any_sync(0xffffffffu, nz);
    if (threadIdx.x == 0) g_valid_is_u8 = nz;
}

// ---------------- helpers ----------------
__device__ __forceinline__ uint32_t smem_u32(const void* p) {
    uint32_t a;
    asm("{ .reg .u64 t; cvta.to.shared.u64 t, %1; cvt.u32.u64 %0, t; }" : "=r"(a) : "l"(p));
    return a;
}
__device__ __forceinline__ void cp16(uint32_t dst, const void* src, uint32_t nbytes) {
    asm volatile("cp.async.cg.shared.global [%0], [%1], 16, %2;"
                 :: "r"(dst), "l"(src), "r"(nbytes) : "memory");
}
#define CP_COMMIT() asm volatile("cp.async.commit_group;" ::: "memory")
#define CP_WAIT1()  asm volatile("cp.async.wait_group 1;" ::: "memory")

__device__ __forceinline__ uint32_t f2tf32(float f) {
    uint32_t t;
    asm("cvt.rna.tf32.f32 %0, %1;" : "=r"(t) : "f"(f));
    return t;
}
__device__ __forceinline__ void mma_tf32(float& d0, float& d1, float& d2, float& d3,
                                         uint32_t a0, uint32_t a1, uint32_t a2, uint32_t a3,
                                         uint32_t b0, uint32_t b1) {
    asm volatile(
        "mma.sync.aligned.m16n8k8.row.col.f32.tf32.tf32.f32 "
        "{%0,%1,%2,%3}, {%4,%5,%6,%7}, {%8,%9}, {%0,%1,%2,%3};"
        : "+f"(d0), "+f"(d1), "+f"(d2), "+f"(d3)
        : "r"(a0), "r"(a1), "r"(a2), "r"(a3), "r"(b0), "r"(b1));
}

struct Pref { int idx[4]; unsigned val; };

// ---------------- main kernel ----------------
__global__ void __launch_bounds__(THREADS, 1)
spconv_mma(const float* __restrict__ feat,
           const float* __restrict__ weight,
           const float* __restrict__ bias,
           const int* __restrict__ kidx,
           const unsigned char* __restrict__ kvalid,
           float* __restrict__ out,
           int N)
{
    extern __shared__ __align__(16) char smem[];
    const uint32_t sb = smem_u32(smem);

    const int tid  = threadIdx.x;
    const int w    = tid >> 5;
    const int lane = tid & 31;
    const int gid  = lane >> 2;   // 0..7  (mma row group)
    const int tig  = lane & 3;    // 0..3  (mma thread-in-group)
    const int r4   = lane >> 3;   // 0..3  (gather row base)
    const int ch   = lane & 7;    // 0..7  (gather 16B chunk)
    const bool u8  = (g_valid_is_u8 != 0);
    const int* kvalid32 = (const int*)kvalid;

    // ---- pack weights into smem (frag-ordered, tf32-rounded) — same as R3 ----
    for (int i = tid; i < KVOL * 1024; i += THREADS) {
        int tap = i >> 10, d = i & 1023;
        int p = d >> 7, ln = (d >> 2) & 31, q = d & 3;
        int f = 2 * p + (q >> 1);
        int ks = f >> 2, nt = f & 3;
        int tg = ln & 3, gd = ln >> 2;
        int c = ks * 8 + tg + ((q & 1) ? 4 : 0);
        int j = nt * 8 + gd;
        ((uint32_t*)smem)[(size_t)tap * 1024 + d] = f2tf32(weight[(size_t)tap * 1024 + c * 32 + j]);
    }
    __syncthreads();   // only CTA-wide sync; mainloop is warp-local

    // bias fragments
    float2 bb[4];
    #pragma unroll
    for (int nt = 0; nt < 4; nt++) {
        bb[nt].x = bias[nt * 8 + tig * 2 + 0];
        bb[nt].y = bias[nt * 8 + tig * 2 + 1];
    }

    const int ntiles = (N + ROWS_W - 1) / ROWS_W;
    const int TW     = gridDim.x * WARPS;            // total warps
    const int gw     = blockIdx.x * WARPS + w;       // my warp id

    int myT = 0;
    for (int t = gw; t < ntiles; t += TW) myT++;
    const int total = myT * KVOL;
    if (total == 0) return;

    // my smem slice bases
    const uint32_t aBase = sb + WBYTES + (uint32_t)(w * NSTAGE) * SLICE;
    const char*    fbase = (const char*)feat;

    // per-lane gather dst offsets within a slice (rows r4+4q, chunk ch, swizzled)
    uint32_t dsto[4];
    #pragma unroll
    for (int q = 0; q < 4; q++) {
        int r = r4 + 4 * q;
        dsto[q] = (uint32_t)r * 128 + (uint32_t)((ch ^ (r & 7)) << 4);
    }

    auto load_idx = [&](int S, int tap, Pref& P) {
        int base = S * ROWS_W + r4;
        unsigned vm = 0;
        #pragma unroll
        for (int q = 0; q < 4; q++) {
            int g = base + 4 * q;
            int id = 0; bool va = false;
            if (S < ntiles && g < N) {
                size_t o = (size_t)tap * N + g;
                id = kidx[o];
                va = u8 ? (kvalid[o] != 0) : (kvalid32[o] != 0);
            }
            P.idx[q] = id;
            vm |= va ? (1u << q) : 0u;
        }
        P.val = vm;
    };
    auto issue = [&](const Pref& P, int stage) {
        uint32_t ab = aBase + (uint32_t)stage * SLICE;
        #pragma unroll
        for (int q = 0; q < 4; q++) {
            const char* src = fbase + ((size_t)(uint32_t)P.idx[q] << 7) + (ch << 4);
            cp16(ab + dsto[q], src, ((P.val >> q) & 1u) ? 16u : 0u);
        }
    };

    // ---- prologue ----
    Pref Pa;
    load_idx(gw, 0, Pa);
    issue(Pa, 0); CP_COMMIT();
    if (total > 1) { load_idx(gw, 1, Pa); issue(Pa, 1); }
    CP_COMMIT();
    if (total > 2) load_idx(gw, 2, Pa);

    int ptap = 3, pS = gw;                 // idx-prefetch cursor (job jl+3)
    if (ptap >= KVOL) { ptap -= KVOL; pS += TW; }
    int ctap = 0, cS = gw;                 // compute cursor

    float acc[4][4];
    #pragma unroll
    for (int nt = 0; nt < 4; nt++)
        #pragma unroll
        for (int r = 0; r < 4; r++) acc[nt][r] = 0.0f;

    for (int jl = 0; jl < total; jl++) {
        CP_WAIT1();
        __syncwarp();

        // issue gather for job jl+2
        if (jl + 2 < total) issue(Pa, (jl + 2) % NSTAGE);
        CP_COMMIT();

        // prefetch idx for job jl+3
        if (jl + 3 < total) {
            load_idx(pS, ptap, Pa);
            if (++ptap == KVOL) { ptap = 0; pS += TW; }
        }

        // ---- compute tap ctap from stage jl%NSTAGE ----
        const char* Ab = (const char*)smem + WBYTES
                       + (size_t)(w * NSTAGE + jl % NSTAGE) * SLICE;

        const float4* wp = (const float4*)(smem + (size_t)ctap * W_TAP);
        const char* pA = Ab + (size_t)gid * 128;
        const char* pB = Ab + (size_t)(gid + 8) * 128;

        #pragma unroll
        for (int ks = 0; ks < 4; ks++) {
            float4 bf0 = wp[(ks * 2 + 0) * 32 + lane];
            float4 bf1 = wp[(ks * 2 + 1) * 32 + lane];
            const uint32_t c0 = (uint32_t)(((2 * ks)     ^ gid) << 4) + tig * 4;
            const uint32_t c1 = (uint32_t)(((2 * ks + 1) ^ gid) << 4) + tig * 4;
            uint32_t a0 = f2tf32(*(const float*)(pA + c0));
            uint32_t a1 = f2tf32(*(const float*)(pB + c0));
            uint32_t a2 = f2tf32(*(const float*)(pA + c1));
            uint32_t a3 = f2tf32(*(const float*)(pB + c1));
            #pragma unroll
            for (int nt = 0; nt < 4; nt++) {
                float4 v = (nt >> 1) ? bf1 : bf0;
                uint32_t b0 = (nt & 1) ? __float_as_uint(v.z) : __float_as_uint(v.x);
                uint32_t b1 = (nt & 1) ? __float_as_uint(v.w) : __float_as_uint(v.y);
                mma_tf32(acc[nt][0], acc[nt][1], acc[nt][2], acc[nt][3],
                         a0, a1, a2, a3, b0, b1);
            }
        }

        // ---- end of tile: epilogue ----
        if (++ctap == KVOL) {
            int gr = cS * ROWS_W + gid;
            #pragma unroll
            for (int nt = 0; nt < 4; nt++) {
                int col = nt * 8 + tig * 2;
                if (gr < N) {
                    float2 o = { acc[nt][0] + bb[nt].x, acc[nt][1] + bb[nt].y };
                    *(float2*)(out + (size_t)gr * COUT + col) = o;
                }
                if (gr + 8 < N) {
                    float2 o = { acc[nt][2] + bb[nt].x, acc[nt][3] + bb[nt].y };
                    *(float2*)(out + (size_t)(gr + 8) * COUT + col) = o;
                }
                acc[nt][0] = acc[nt][1] = acc[nt][2] = acc[nt][3] = 0.0f;
            }
            ctap = 0;
            cS += TW;
        }
    }
}

extern "C" void kernel_launch(void* const* d_in, const int* in_sizes, int n_in,
                              void* d_out, int out_size) {
    const float*         feat   = (const float*)d_in[0];          // [N, 32]
    const float*         weight = (const float*)d_in[1];          // [27, 32, 32]
    const float*         bias   = (const float*)d_in[2];          // [32]
    const int*           kidx   = (const int*)d_in[3];            // [27, N]
    const unsigned char* kvalid = (const unsigned char*)d_in[4];  // [27, N] bool
    float* out = (float*)d_out;

    const int N = in_sizes[0] / CIN;

    int sms = 148;
    cudaDeviceGetAttribute(&sms, cudaDevAttrMultiProcessorCount, 0);

    cudaFuncSetAttribute(spconv_mma, cudaFuncAttributeMaxDynamicSharedMemorySize, SMEM_TOTAL);

    detect_valid_dtype<<<1, 32>>>(kvalid, 16384);
    spconv_mma<<<sms, THREADS, SMEM_TOTAL>>>(feat, weight, bias, kidx, kvalid, out, N);
}